// round 4
// baseline (speedup 1.0000x reference)
#include <cuda_runtime.h>
#include <math.h>

#define BATCH    8192
#define DLAT     512
#define NCB      2
#define KCODES   8192
#define DSUB     256

#define BM 128
#define BN 128
#define BK 16

// Scratch (no allocations allowed)
__device__ unsigned long long g_packed[BATCH * NCB];   // (sortable_u<<32)|k
__device__ int    g_counts[NCB * KCODES];
__device__ float  g_zsq[BATCH * NCB];
__device__ double g_sse;

// ---------------------------------------------------------------------------
__global__ void init_kernel() {
    int i = blockIdx.x * blockDim.x + threadIdx.x;
    if (i < BATCH * NCB)  g_packed[i] = 0xFFFFFFFFFFFFFFFFull;
    if (i < NCB * KCODES) g_counts[i] = 0;
    if (i == 0)           g_sse = 0.0;
}

// ---------------------------------------------------------------------------
// z_sq[b,n] — numerics proven to match reference in R3; DO NOT change order.
__global__ void zsq_kernel(const float* __restrict__ z) {
    int w    = blockIdx.x * (blockDim.x >> 5) + (threadIdx.x >> 5);  // 0..16383
    int lane = threadIdx.x & 31;
    const float* row = z + (size_t)w * DSUB;
    float s = 0.f;
#pragma unroll
    for (int t = 0; t < DSUB / 32; t++) {
        float v  = row[lane + 32 * t];
        float sq = __fmul_rn(v, v);
        s = __fadd_rn(s, sq);
    }
#pragma unroll
    for (int o = 16; o; o >>= 1)
        s = __fadd_rn(s, __shfl_down_sync(0xffffffffu, s, o));
    if (lane == 0) g_zsq[w] = s;
}

// ---------------------------------------------------------------------------
// Fused exact-fp32 GEMM using packed fma.rn.f32x2 (bit-exact vs scalar FFMA:
// same accumulator, same ascending-k order, each lane IEEE fp32 RN).
// A is stored DUPLICATED in smem ({v,v} pairs) so a-operands load as b64
// with no packing movs; B pairs are naturally contiguous.
__global__ __launch_bounds__(256, 2)
void gemm_argmin_kernel(const float* __restrict__ z, const float* __restrict__ emb) {
    __shared__ float As2[2][BK][2 * BM];   // duplicated pairs: 32 KB
    __shared__ float Bs[2][BK][BN];        // 16 KB   (total 48 KB)

    const int n  = blockIdx.z;
    const int bm = blockIdx.y;
    const int bn = blockIdx.x;
    const int tid = threadIdx.x;
    const int tx = tid & 15;     // col group (k-codes)
    const int ty = tid >> 4;     // row group (batch)

    const float* Ag = z   + (size_t)(bm * BM) * DLAT + n * DSUB;
    const float* Bg = emb + (size_t)n * KCODES * DSUB + (size_t)(bn * BN) * DSUB;

    unsigned long long acc2[8][4];
#pragma unroll
    for (int i = 0; i < 8; i++)
#pragma unroll
        for (int jp = 0; jp < 4; jp++) acc2[i][jp] = 0ull;

    auto dup_pack = [](float v) -> unsigned long long {
        unsigned long long r;
        asm("mov.b64 %0, {%1, %1};" : "=l"(r) : "f"(v));
        return r;
    };

    auto loadA = [&](int buf, int kb) {
#pragma unroll
        for (int u = 0; u < 2; u++) {
            int s = tid + u * 256;
            int r = s & 127;
            int c = (s >> 7) * 4;
            float4 v = *(const float4*)(Ag + (size_t)r * DLAT + kb + c);
            *(unsigned long long*)&As2[buf][c + 0][2 * r] = dup_pack(v.x);
            *(unsigned long long*)&As2[buf][c + 1][2 * r] = dup_pack(v.y);
            *(unsigned long long*)&As2[buf][c + 2][2 * r] = dup_pack(v.z);
            *(unsigned long long*)&As2[buf][c + 3][2 * r] = dup_pack(v.w);
        }
    };
    auto loadB = [&](int buf, int kb) {
#pragma unroll
        for (int u = 0; u < 2; u++) {
            int s = tid + u * 256;
            int r = s & 127;
            int c = (s >> 7) * 4;
            float4 v = *(const float4*)(Bg + (size_t)r * DSUB + kb + c);
            Bs[buf][c + 0][r] = v.x; Bs[buf][c + 1][r] = v.y;
            Bs[buf][c + 2][r] = v.z; Bs[buf][c + 3][r] = v.w;
        }
    };

    loadA(0, 0);
    loadB(0, 0);
    __syncthreads();

    for (int kb = 0; kb < DSUB; kb += BK) {
        int cur = (kb / BK) & 1;
        int nxt = cur ^ 1;
        if (kb + BK < DSUB) { loadA(nxt, kb + BK); loadB(nxt, kb + BK); }

#pragma unroll
        for (int kk = 0; kk < BK; kk++) {
            unsigned long long a2[8], b2[4];
            // a pairs: duplicated {a_i,a_i}, 16B-aligned v2.u64 loads
            {
                const float* ap = &As2[cur][kk][2 * (ty * 8)];
#pragma unroll
                for (int q = 0; q < 4; q++)
                    asm("ld.shared.v2.u64 {%0, %1}, [%2];"
                        : "=l"(a2[2 * q]), "=l"(a2[2 * q + 1])
                        : "r"((unsigned)__cvta_generic_to_shared(ap + 4 * q)));
            }
            // b pairs: naturally contiguous {b_{2j}, b_{2j+1}}
            {
                const float* bp = &Bs[cur][kk][tx * 8];
#pragma unroll
                for (int q = 0; q < 2; q++)
                    asm("ld.shared.v2.u64 {%0, %1}, [%2];"
                        : "=l"(b2[2 * q]), "=l"(b2[2 * q + 1])
                        : "r"((unsigned)__cvta_generic_to_shared(bp + 4 * q)));
            }
#pragma unroll
            for (int i = 0; i < 8; i++)
#pragma unroll
                for (int jp = 0; jp < 4; jp++)
                    asm("fma.rn.f32x2 %0, %1, %2, %3;"
                        : "=l"(acc2[i][jp])
                        : "l"(a2[i]), "l"(b2[jp]), "l"(acc2[i][jp]));
        }
        __syncthreads();
    }

    // Epilogue: u = RN(zsq - 2*c); argmin with lowest-k tie-break
#pragma unroll
    for (int i = 0; i < 8; i++) {
        int b = bm * BM + ty * 8 + i;
        float zsq = g_zsq[(size_t)b * NCB + n];
        unsigned long long key = 0xFFFFFFFFFFFFFFFFull;
#pragma unroll
        for (int jp = 0; jp < 4; jp++) {
            float c0, c1;
            asm("mov.b64 {%0, %1}, %2;" : "=f"(c0), "=f"(c1) : "l"(acc2[i][jp]));
#pragma unroll
            for (int h = 0; h < 2; h++) {
                float cv = h ? c1 : c0;
                float u = __fmaf_rn(-2.0f, cv, zsq);
                unsigned ub = __float_as_uint(u);
                ub = (ub & 0x80000000u) ? ~ub : (ub | 0x80000000u);
                unsigned long long cand =
                    ((unsigned long long)ub << 32) |
                    (unsigned)(bn * BN + tx * 8 + 2 * jp + h);
                if (cand < key) key = cand;
            }
        }
#pragma unroll
        for (int o = 1; o < 16; o <<= 1) {
            unsigned long long other = __shfl_xor_sync(0xffffffffu, key, o);
            if (other < key) key = other;
        }
        if (tx == 0) atomicMin(&g_packed[(size_t)b * NCB + n], key);
    }
}

// ---------------------------------------------------------------------------
// out = RN(z + RN(z_q - z)); indices, commitment SSE, usage counts.
__global__ void gather_kernel(const float* __restrict__ z,
                              const float* __restrict__ emb,
                              float* __restrict__ out) {
    int w    = blockIdx.x * (blockDim.x >> 5) + (threadIdx.x >> 5);  // 0..16383
    int lane = threadIdx.x & 31;
    int b = w >> 1;
    int n = w & 1;

    unsigned long long key = g_packed[w];
    int idx = (int)(key & 0xFFFFFFFFull);

    if (lane == 0) {
        out[(size_t)BATCH * DLAT + w] = (float)idx;
        atomicAdd(&g_counts[n * KCODES + idx], 1);
    }

    const float* e  = emb + ((size_t)n * KCODES + idx) * DSUB;
    const float* zp = z   + (size_t)b * DLAT + n * DSUB;
    float*       op = out + (size_t)b * DLAT + n * DSUB;

    float s = 0.f;
#pragma unroll
    for (int t = 0; t < DSUB / 32; t++) {
        float ev = e[lane + 32 * t];
        float zv = zp[lane + 32 * t];
        float r  = __fsub_rn(ev, zv);
        op[lane + 32 * t] = __fadd_rn(zv, r);
        float d = __fsub_rn(zv, ev);
        s = __fmaf_rn(d, d, s);
    }
#pragma unroll
    for (int o = 16; o; o >>= 1) s += __shfl_down_sync(0xffffffffu, s, o);
    if (lane == 0) atomicAdd(&g_sse, (double)s);
}

// ---------------------------------------------------------------------------
__global__ void final_kernel(float* __restrict__ out) {
    __shared__ float red[256];
    int tid = threadIdx.x;
    float s = 0.f;
    for (int k = tid; k < KCODES; k += 256) {
        float p = (float)(g_counts[k] + g_counts[KCODES + k]) /
                  (float)(NCB * BATCH);
        s += p * logf(p + 1e-10f);
    }
    red[tid] = s;
    __syncthreads();
    for (int o = 128; o; o >>= 1) {
        if (tid < o) red[tid] += red[tid + o];
        __syncthreads();
    }
    if (tid == 0) {
        size_t off = (size_t)BATCH * DLAT + (size_t)BATCH * NCB;
        out[off + 0] = (float)(0.25 * (g_sse / (double)((size_t)BATCH * DLAT)));
        out[off + 1] = 0.0f;
        out[off + 2] = expf(-red[0]);
    }
}

// ---------------------------------------------------------------------------
extern "C" void kernel_launch(void* const* d_in, const int* in_sizes, int n_in,
                              void* d_out, int out_size) {
    const float* z   = (const float*)d_in[0];   // [8192, 512]
    const float* emb = (const float*)d_in[1];   // [2, 8192, 256]
    float* out = (float*)d_out;

    init_kernel<<<64, 256>>>();
    zsq_kernel<<<(BATCH * NCB) / 8, 256>>>(z);

    dim3 grid(KCODES / BN, BATCH / BM, NCB);
    gemm_argmin_kernel<<<grid, 256>>>(z, emb);

    gather_kernel<<<(BATCH * NCB) / 8, 256>>>(z, emb, out);
    final_kernel<<<1, 256>>>(out);
}

// round 5
// speedup vs baseline: 4.0113x; 4.0113x over previous
#include <cuda_runtime.h>
#include <cuda_bf16.h>
#include <math.h>

#define BATCH    8192
#define DLAT     512
#define NCB      2
#define KCODES   8192
#define DSUB     256

#define BM 128
#define BN 128
#define KS 32
#define CAP 112
#define MARGIN_F 8e-5f

#define NROWS (BATCH * NCB)     // 16384

// Scratch (static device globals; no allocations)
__device__ __align__(16) __nv_bfloat16 g_zbf[BATCH * DLAT];
__device__ __align__(16) __nv_bfloat16 g_ebf[NCB * KCODES * DSUB];
__device__ uint2    g_cand[NROWS * CAP];   // {float bits of c_approx, k}
__device__ int      g_cnt[NROWS];
__device__ unsigned g_gmax[NROWS];         // sortable-encoded max c_approx
__device__ unsigned long long g_packed[NROWS];  // (sortable(u)<<32)|k
__device__ int      g_counts[NCB * KCODES];
__device__ float    g_zsq[NROWS];
__device__ double   g_sse;

__device__ __forceinline__ unsigned f_enc(float f) {   // monotone float->uint
    unsigned b = __float_as_uint(f);
    return (b & 0x80000000u) ? ~b : (b | 0x80000000u);
}
__device__ __forceinline__ float f_dec(unsigned u) {
    return __uint_as_float((u & 0x80000000u) ? (u ^ 0x80000000u) : ~u);
}

// ---------------------------------------------------------------------------
__global__ void init_kernel() {
    int i = blockIdx.x * blockDim.x + threadIdx.x;
    if (i < NROWS) { g_cnt[i] = 0; g_gmax[i] = 0u; }
    if (i < NCB * KCODES) g_counts[i] = 0;
    if (i == 0) g_sse = 0.0;
}

// ---------------------------------------------------------------------------
__global__ void convert_kernel(const float* __restrict__ z,
                               const float* __restrict__ emb) {
    int i = blockIdx.x * blockDim.x + threadIdx.x;   // 0 .. 4M-1 (both equal size)
    if (i < BATCH * DLAT)        g_zbf[i] = __float2bfloat16_rn(z[i]);
    if (i < NCB * KCODES * DSUB) g_ebf[i] = __float2bfloat16_rn(emb[i]);
}

// ---------------------------------------------------------------------------
// z_sq — numerics proven in R3; unchanged.
__global__ void zsq_kernel(const float* __restrict__ z) {
    int w    = blockIdx.x * (blockDim.x >> 5) + (threadIdx.x >> 5);
    int lane = threadIdx.x & 31;
    const float* row = z + (size_t)w * DSUB;
    float s = 0.f;
#pragma unroll
    for (int t = 0; t < DSUB / 32; t++) {
        float v  = row[lane + 32 * t];
        s = __fadd_rn(s, __fmul_rn(v, v));
    }
#pragma unroll
    for (int o = 16; o; o >>= 1)
        s = __fadd_rn(s, __shfl_down_sync(0xffffffffu, s, o));
    if (lane == 0) g_zsq[w] = s;
}

// ---------------------------------------------------------------------------
// Screening: bf16 mma.sync GEMM (c_approx = Z_n * E_n^T, fp32 accum).
// Per (row, 128-col block): keep local max of c and all within MARGIN of it.
__global__ __launch_bounds__(256, 2)
void screen_kernel() {
    __shared__ __nv_bfloat16 As[BM][KS + 8];
    __shared__ __nv_bfloat16 Bs[BN][KS + 8];
    __shared__ float redmax[2][BM];

    const int n  = blockIdx.z;
    const int bm = blockIdx.y;
    const int bn = blockIdx.x;
    const int tid  = threadIdx.x;
    const int wid  = tid >> 5;
    const int lane = tid & 31;
    const int wm = wid & 3;       // 4 warps along M (32 rows each)
    const int wn = wid >> 2;      // 2 warps along N (64 cols each)
    const int g  = lane >> 2;     // groupID
    const int t  = lane & 3;      // thread-in-group

    const __nv_bfloat16* Ag = g_zbf + (size_t)(bm * BM) * DLAT + n * DSUB;
    const __nv_bfloat16* Bg = g_ebf + (size_t)n * KCODES * DSUB + (size_t)(bn * BN) * DSUB;

    float acc[2][8][4];
#pragma unroll
    for (int mt = 0; mt < 2; mt++)
#pragma unroll
        for (int nt = 0; nt < 8; nt++)
#pragma unroll
            for (int q = 0; q < 4; q++) acc[mt][nt][q] = 0.f;

    for (int kb = 0; kb < DSUB; kb += KS) {
        // Load tiles: each row = KS halves = 64B = 4×uint4; 512 uint4/tile
#pragma unroll
        for (int u = 0; u < 2; u++) {
            int s = tid + u * 256;
            int r = s >> 2;
            int q = s & 3;
            *(uint4*)&As[r][q * 8] = *(const uint4*)(Ag + (size_t)r * DLAT + kb + q * 8);
            *(uint4*)&Bs[r][q * 8] = *(const uint4*)(Bg + (size_t)r * DSUB + kb + q * 8);
        }
        __syncthreads();

#pragma unroll
        for (int ks = 0; ks < KS; ks += 16) {
            unsigned bb[8][2];
#pragma unroll
            for (int nt = 0; nt < 8; nt++) {
                const __nv_bfloat16* bp = &Bs[wn * 64 + nt * 8 + g][ks + 2 * t];
                bb[nt][0] = *(const unsigned*)bp;
                bb[nt][1] = *(const unsigned*)(bp + 8);
            }
#pragma unroll
            for (int mt = 0; mt < 2; mt++) {
                const __nv_bfloat16* ap = &As[wm * 32 + mt * 16 + g][ks + 2 * t];
                unsigned a0 = *(const unsigned*)ap;
                unsigned a1 = *(const unsigned*)(ap + 8 * (KS + 8));
                unsigned a2 = *(const unsigned*)(ap + 8);
                unsigned a3 = *(const unsigned*)(ap + 8 * (KS + 8) + 8);
#pragma unroll
                for (int nt = 0; nt < 8; nt++) {
                    asm volatile(
                        "mma.sync.aligned.m16n8k16.row.col.f32.bf16.bf16.f32 "
                        "{%0,%1,%2,%3}, {%4,%5,%6,%7}, {%8,%9}, {%0,%1,%2,%3};"
                        : "+f"(acc[mt][nt][0]), "+f"(acc[mt][nt][1]),
                          "+f"(acc[mt][nt][2]), "+f"(acc[mt][nt][3])
                        : "r"(a0), "r"(a1), "r"(a2), "r"(a3),
                          "r"(bb[nt][0]), "r"(bb[nt][1]));
                }
            }
        }
        __syncthreads();
    }

    // Per-row local max (this block's 128 cols), then candidate emission.
    float m_lo[2], m_hi[2];
#pragma unroll
    for (int mt = 0; mt < 2; mt++) {
        float lo = -1e30f, hi = -1e30f;
#pragma unroll
        for (int nt = 0; nt < 8; nt++) {
            lo = fmaxf(lo, fmaxf(acc[mt][nt][0], acc[mt][nt][1]));
            hi = fmaxf(hi, fmaxf(acc[mt][nt][2], acc[mt][nt][3]));
        }
#pragma unroll
        for (int o = 1; o < 4; o <<= 1) {
            lo = fmaxf(lo, __shfl_xor_sync(0xffffffffu, lo, o));
            hi = fmaxf(hi, __shfl_xor_sync(0xffffffffu, hi, o));
        }
        m_lo[mt] = lo; m_hi[mt] = hi;
        if (t == 0) {
            redmax[wn][wm * 32 + mt * 16 + g]     = lo;
            redmax[wn][wm * 32 + mt * 16 + g + 8] = hi;
        }
    }
    __syncthreads();

#pragma unroll
    for (int mt = 0; mt < 2; mt++) {
#pragma unroll
        for (int half = 0; half < 2; half++) {
            int lr = wm * 32 + mt * 16 + g + 8 * half;
            float full = fmaxf(redmax[0][lr], redmax[1][lr]);
            int rowid = (bm * BM + lr) * NCB + n;
            if (wn == 0 && t == 0)
                atomicMax(&g_gmax[rowid], f_enc(full));
            float thresh = full - MARGIN_F;
#pragma unroll
            for (int nt = 0; nt < 8; nt++) {
#pragma unroll
                for (int e = 0; e < 2; e++) {
                    float v = acc[mt][nt][2 * half + e];
                    if (v >= thresh) {
                        int slot = atomicAdd(&g_cnt[rowid], 1);
                        if (slot < CAP) {
                            int k = bn * BN + wn * 64 + nt * 8 + 2 * t + e;
                            g_cand[rowid * CAP + slot] =
                                make_uint2(__float_as_uint(v), (unsigned)k);
                        }
                    }
                }
            }
        }
    }
}

// ---------------------------------------------------------------------------
// Exact rescore of surviving candidates: ascending-d single-accumulator FMA
// chain (bit-identical to the R3-proven numerics). One warp per row.
__global__ __launch_bounds__(256)
void rescore_kernel(const float* __restrict__ z, const float* __restrict__ emb) {
    __shared__ float sz[8][DSUB];
    int wid  = threadIdx.x >> 5;
    int lane = threadIdx.x & 31;
    int row  = blockIdx.x * 8 + wid;          // 0..16383
    int b = row >> 1;
    int n = row & 1;

    const float* zp = z + (size_t)b * DLAT + n * DSUB;
#pragma unroll
    for (int tq = 0; tq < DSUB / 32; tq++)
        sz[wid][lane + 32 * tq] = zp[lane + 32 * tq];
    __syncwarp();

    float zsq    = g_zsq[row];
    float thresh = f_dec(g_gmax[row]) - MARGIN_F;
    int cnt = g_cnt[row]; if (cnt > CAP) cnt = CAP;

    unsigned long long key = 0xFFFFFFFFFFFFFFFFull;
    for (int c = lane; c < cnt; c += 32) {
        uint2 cd = g_cand[row * CAP + c];
        if (__uint_as_float(cd.x) < thresh) continue;
        int k = (int)cd.y;
        const float* e = emb + ((size_t)n * KCODES + k) * DSUB;
        float acc = 0.f;
#pragma unroll 8
        for (int d = 0; d < DSUB; d++)
            acc = __fmaf_rn(sz[wid][d], e[d], acc);
        float u = __fmaf_rn(-2.0f, acc, zsq);
        unsigned long long cand = ((unsigned long long)f_enc(u) << 32) | (unsigned)k;
        // NB: f_enc is monotone increasing, so min key == min (u, k) lexicographic
        if (cand < key) key = cand;
    }
#pragma unroll
    for (int o = 16; o; o >>= 1) {
        unsigned long long other = __shfl_xor_sync(0xffffffffu, key, o);
        if (other < key) key = other;
    }
    if (lane == 0) g_packed[row] = key;
}

// ---------------------------------------------------------------------------
// out = RN(z + RN(z_q - z)); indices, commitment SSE, usage counts.
__global__ void gather_kernel(const float* __restrict__ z,
                              const float* __restrict__ emb,
                              float* __restrict__ out) {
    int w    = blockIdx.x * (blockDim.x >> 5) + (threadIdx.x >> 5);
    int lane = threadIdx.x & 31;
    int b = w >> 1;
    int n = w & 1;

    int idx = (int)(g_packed[w] & 0xFFFFFFFFull);

    if (lane == 0) {
        out[(size_t)BATCH * DLAT + w] = (float)idx;
        atomicAdd(&g_counts[n * KCODES + idx], 1);
    }

    const float* e  = emb + ((size_t)n * KCODES + idx) * DSUB;
    const float* zp = z   + (size_t)b * DLAT + n * DSUB;
    float*       op = out + (size_t)b * DLAT + n * DSUB;

    float s = 0.f;
#pragma unroll
    for (int t = 0; t < DSUB / 32; t++) {
        float ev = e[lane + 32 * t];
        float zv = zp[lane + 32 * t];
        float r  = __fsub_rn(ev, zv);
        op[lane + 32 * t] = __fadd_rn(zv, r);
        float d = __fsub_rn(zv, ev);
        s = __fmaf_rn(d, d, s);
    }
#pragma unroll
    for (int o = 16; o; o >>= 1) s += __shfl_down_sync(0xffffffffu, s, o);
    if (lane == 0) atomicAdd(&g_sse, (double)s);
}

// ---------------------------------------------------------------------------
__global__ void final_kernel(float* __restrict__ out) {
    __shared__ float red[256];
    int tid = threadIdx.x;
    float s = 0.f;
    for (int k = tid; k < KCODES; k += 256) {
        float p = (float)(g_counts[k] + g_counts[KCODES + k]) /
                  (float)(NCB * BATCH);
        s += p * logf(p + 1e-10f);
    }
    red[tid] = s;
    __syncthreads();
    for (int o = 128; o; o >>= 1) {
        if (tid < o) red[tid] += red[tid + o];
        __syncthreads();
    }
    if (tid == 0) {
        size_t off = (size_t)BATCH * DLAT + (size_t)NROWS;
        out[off + 0] = (float)(0.25 * (g_sse / (double)((size_t)BATCH * DLAT)));
        out[off + 1] = 0.0f;
        out[off + 2] = expf(-red[0]);
    }
}

// ---------------------------------------------------------------------------
extern "C" void kernel_launch(void* const* d_in, const int* in_sizes, int n_in,
                              void* d_out, int out_size) {
    const float* z   = (const float*)d_in[0];   // [8192, 512]
    const float* emb = (const float*)d_in[1];   // [2, 8192, 256]
    float* out = (float*)d_out;

    init_kernel<<<(NROWS + 255) / 256, 256>>>();
    convert_kernel<<<(BATCH * DLAT + 255) / 256, 256>>>(z, emb);
    zsq_kernel<<<NROWS / 8, 256>>>(z);

    dim3 grid(KCODES / BN, BATCH / BM, NCB);
    screen_kernel<<<grid, 256>>>();

    rescore_kernel<<<NROWS / 8, 256>>>(z, emb);
    gather_kernel<<<NROWS / 8, 256>>>(z, emb, out);
    final_kernel<<<1, 256>>>(out);
}

// round 6
// speedup vs baseline: 4.6493x; 1.1591x over previous
#include <cuda_runtime.h>
#include <cuda_bf16.h>
#include <math.h>

#define BATCH    8192
#define DLAT     512
#define NCB      2
#define KCODES   8192
#define DSUB     256

#define BM 128
#define BN 128
#define KS 32
#define KPAD (KS + 8)
#define CAP 112
#define MARGIN_F 8e-5f

#define NROWS (BATCH * NCB)     // 16384

// Scratch (static device globals; no allocations)
__device__ __align__(16) __nv_bfloat16 g_zbf[BATCH * DLAT];
__device__ __align__(16) __nv_bfloat16 g_ebf[NCB * KCODES * DSUB];
__device__ uint2    g_cand[NROWS * CAP];   // {float bits of c_approx, k}
__device__ int      g_cnt[NROWS];
__device__ unsigned g_gmax[NROWS];         // sortable-encoded max c_approx
__device__ unsigned long long g_packed[NROWS];  // (sortable(u)<<32)|k
__device__ int      g_counts[NCB * KCODES];
__device__ float    g_zsq[NROWS];
__device__ double   g_sse;

__device__ __forceinline__ unsigned f_enc(float f) {   // monotone float->uint
    unsigned b = __float_as_uint(f);
    return (b & 0x80000000u) ? ~b : (b | 0x80000000u);
}
__device__ __forceinline__ float f_dec(unsigned u) {
    return __uint_as_float((u & 0x80000000u) ? (u ^ 0x80000000u) : ~u);
}

__device__ __forceinline__ void cp16(void* s, const void* g) {
    unsigned sa = (unsigned)__cvta_generic_to_shared(s);
    asm volatile("cp.async.ca.shared.global [%0], [%1], 16;" :: "r"(sa), "l"(g));
}

// ---------------------------------------------------------------------------
__global__ void init_kernel() {
    int i = blockIdx.x * blockDim.x + threadIdx.x;
    if (i < NROWS) { g_cnt[i] = 0; g_gmax[i] = 0u; }
    if (i < NCB * KCODES) g_counts[i] = 0;
    if (i == 0) g_sse = 0.0;
}

// ---------------------------------------------------------------------------
__global__ void convert_kernel(const float* __restrict__ z,
                               const float* __restrict__ emb) {
    int i = blockIdx.x * blockDim.x + threadIdx.x;
    if (i < BATCH * DLAT)        g_zbf[i] = __float2bfloat16_rn(z[i]);
    if (i < NCB * KCODES * DSUB) g_ebf[i] = __float2bfloat16_rn(emb[i]);
}

// ---------------------------------------------------------------------------
// z_sq — numerics proven in R3; unchanged.
__global__ void zsq_kernel(const float* __restrict__ z) {
    int w    = blockIdx.x * (blockDim.x >> 5) + (threadIdx.x >> 5);
    int lane = threadIdx.x & 31;
    const float* row = z + (size_t)w * DSUB;
    float s = 0.f;
#pragma unroll
    for (int t = 0; t < DSUB / 32; t++) {
        float v  = row[lane + 32 * t];
        s = __fadd_rn(s, __fmul_rn(v, v));
    }
#pragma unroll
    for (int o = 16; o; o >>= 1)
        s = __fadd_rn(s, __shfl_down_sync(0xffffffffu, s, o));
    if (lane == 0) g_zsq[w] = s;
}

// ---------------------------------------------------------------------------
// Screening: bf16 mma.sync GEMM with LDSM fragment loads + cp.async double
// buffering. Per (row, 128-col block): keep local max and all within MARGIN.
__global__ __launch_bounds__(256, 2)
void screen_kernel() {
    __shared__ __nv_bfloat16 As[2][BM][KPAD];
    __shared__ __nv_bfloat16 Bs[2][BN][KPAD];
    __shared__ float redmax[2][BM];

    const int n  = blockIdx.z;
    const int bm = blockIdx.y;
    const int bn = blockIdx.x;
    const int tid  = threadIdx.x;
    const int wid  = tid >> 5;
    const int lane = tid & 31;
    const int wm = wid & 3;       // 4 warps along M (32 rows each)
    const int wn = wid >> 2;      // 2 warps along N (64 cols each)
    const int g  = lane >> 2;     // groupID
    const int t  = lane & 3;      // thread-in-group

    const __nv_bfloat16* Ag = g_zbf + (size_t)(bm * BM) * DLAT + n * DSUB;
    const __nv_bfloat16* Bg = g_ebf + (size_t)n * KCODES * DSUB + (size_t)(bn * BN) * DSUB;

    float acc[2][8][4];
#pragma unroll
    for (int mt = 0; mt < 2; mt++)
#pragma unroll
        for (int nt = 0; nt < 8; nt++)
#pragma unroll
            for (int q = 0; q < 4; q++) acc[mt][nt][q] = 0.f;

    // async tile loader: 128 rows x 32 halves (64B = 4 chunks of 16B) per tensor
    auto loadTiles = [&](int buf, int kb) {
#pragma unroll
        for (int u = 0; u < 2; u++) {
            int s = tid + u * 256;
            int r = s >> 2;
            int q = s & 3;
            cp16(&As[buf][r][q * 8], Ag + (size_t)r * DLAT + kb + q * 8);
            cp16(&Bs[buf][r][q * 8], Bg + (size_t)r * DSUB + kb + q * 8);
        }
        asm volatile("cp.async.commit_group;");
    };

    // ldmatrix lane-address components (row, col within the x4 quad)
    const int jq   = lane >> 3;           // 0..3  (which 8x8 matrix)
    const int rsub = lane & 7;            // row within matrix

    loadTiles(0, 0);

    for (int kbi = 0; kbi < DSUB / KS; kbi++) {
        int cur = kbi & 1;
        asm volatile("cp.async.wait_group 0;");
        __syncthreads();
        if (kbi + 1 < DSUB / KS) loadTiles(cur ^ 1, (kbi + 1) * KS);

#pragma unroll
        for (int ks = 0; ks < KS; ks += 16) {
            // B fragments: nt pairs via ldmatrix.x4
            unsigned bb[8][2];
#pragma unroll
            for (int np = 0; np < 4; np++) {
                int nbase = wn * 64 + np * 16;
                int row = nbase + ((jq >> 1) << 3) + rsub;
                int col = ks + ((jq & 1) << 3);
                unsigned addr = (unsigned)__cvta_generic_to_shared(&Bs[cur][row][col]);
                asm volatile(
                    "ldmatrix.sync.aligned.m8n8.x4.shared.b16 {%0,%1,%2,%3}, [%4];"
                    : "=r"(bb[2 * np][0]), "=r"(bb[2 * np][1]),
                      "=r"(bb[2 * np + 1][0]), "=r"(bb[2 * np + 1][1])
                    : "r"(addr));
            }
#pragma unroll
            for (int mt = 0; mt < 2; mt++) {
                int mbase = wm * 32 + mt * 16;
                int row = mbase + ((jq & 1) << 3) + rsub;
                int col = ks + ((jq >> 1) << 3);
                unsigned addr = (unsigned)__cvta_generic_to_shared(&As[cur][row][col]);
                unsigned a0, a1, a2, a3;
                asm volatile(
                    "ldmatrix.sync.aligned.m8n8.x4.shared.b16 {%0,%1,%2,%3}, [%4];"
                    : "=r"(a0), "=r"(a1), "=r"(a2), "=r"(a3) : "r"(addr));
#pragma unroll
                for (int nt = 0; nt < 8; nt++) {
                    asm volatile(
                        "mma.sync.aligned.m16n8k16.row.col.f32.bf16.bf16.f32 "
                        "{%0,%1,%2,%3}, {%4,%5,%6,%7}, {%8,%9}, {%0,%1,%2,%3};"
                        : "+f"(acc[mt][nt][0]), "+f"(acc[mt][nt][1]),
                          "+f"(acc[mt][nt][2]), "+f"(acc[mt][nt][3])
                        : "r"(a0), "r"(a1), "r"(a2), "r"(a3),
                          "r"(bb[nt][0]), "r"(bb[nt][1]));
                }
            }
        }
        __syncthreads();
    }

    // Per-row local max (this block's 128 cols), then candidate emission.
#pragma unroll
    for (int mt = 0; mt < 2; mt++) {
        float lo = -1e30f, hi = -1e30f;
#pragma unroll
        for (int nt = 0; nt < 8; nt++) {
            lo = fmaxf(lo, fmaxf(acc[mt][nt][0], acc[mt][nt][1]));
            hi = fmaxf(hi, fmaxf(acc[mt][nt][2], acc[mt][nt][3]));
        }
#pragma unroll
        for (int o = 1; o < 4; o <<= 1) {
            lo = fmaxf(lo, __shfl_xor_sync(0xffffffffu, lo, o));
            hi = fmaxf(hi, __shfl_xor_sync(0xffffffffu, hi, o));
        }
        if (t == 0) {
            redmax[wn][wm * 32 + mt * 16 + g]     = lo;
            redmax[wn][wm * 32 + mt * 16 + g + 8] = hi;
        }
    }
    __syncthreads();

#pragma unroll
    for (int mt = 0; mt < 2; mt++) {
#pragma unroll
        for (int half = 0; half < 2; half++) {
            int lr = wm * 32 + mt * 16 + g + 8 * half;
            float full = fmaxf(redmax[0][lr], redmax[1][lr]);
            int rowid = (bm * BM + lr) * NCB + n;
            if (wn == 0 && t == 0)
                atomicMax(&g_gmax[rowid], f_enc(full));
            float thresh = full - MARGIN_F;
#pragma unroll
            for (int nt = 0; nt < 8; nt++) {
#pragma unroll
                for (int e = 0; e < 2; e++) {
                    float v = acc[mt][nt][2 * half + e];
                    if (v >= thresh) {
                        int slot = atomicAdd(&g_cnt[rowid], 1);
                        if (slot < CAP) {
                            int k = bn * BN + wn * 64 + nt * 8 + 2 * t + e;
                            g_cand[rowid * CAP + slot] =
                                make_uint2(__float_as_uint(v), (unsigned)k);
                        }
                    }
                }
            }
        }
    }
}

// ---------------------------------------------------------------------------
// Exact rescore: ascending-d single-accumulator FMA chain (R3-proven).
__global__ __launch_bounds__(256)
void rescore_kernel(const float* __restrict__ z, const float* __restrict__ emb) {
    __shared__ float sz[8][DSUB];
    int wid  = threadIdx.x >> 5;
    int lane = threadIdx.x & 31;
    int row  = blockIdx.x * 8 + wid;          // 0..16383
    int b = row >> 1;
    int n = row & 1;

    const float* zp = z + (size_t)b * DLAT + n * DSUB;
#pragma unroll
    for (int tq = 0; tq < DSUB / 32; tq++)
        sz[wid][lane + 32 * tq] = zp[lane + 32 * tq];
    __syncwarp();

    float zsq    = g_zsq[row];
    float thresh = f_dec(g_gmax[row]) - MARGIN_F;
    int cnt = g_cnt[row]; if (cnt > CAP) cnt = CAP;

    unsigned long long key = 0xFFFFFFFFFFFFFFFFull;
    for (int c = lane; c < cnt; c += 32) {
        uint2 cd = g_cand[row * CAP + c];
        if (__uint_as_float(cd.x) < thresh) continue;
        int k = (int)cd.y;
        const float* e = emb + ((size_t)n * KCODES + k) * DSUB;
        float acc = 0.f;
#pragma unroll 8
        for (int d = 0; d < DSUB; d++)
            acc = __fmaf_rn(sz[wid][d], e[d], acc);
        float u = __fmaf_rn(-2.0f, acc, zsq);
        unsigned long long cand = ((unsigned long long)f_enc(u) << 32) | (unsigned)k;
        if (cand < key) key = cand;
    }
#pragma unroll
    for (int o = 16; o; o >>= 1) {
        unsigned long long other = __shfl_xor_sync(0xffffffffu, key, o);
        if (other < key) key = other;
    }
    if (lane == 0) g_packed[row] = key;
}

// ---------------------------------------------------------------------------
// out = RN(z + RN(z_q - z)); indices, commitment SSE, usage counts.
__global__ void gather_kernel(const float* __restrict__ z,
                              const float* __restrict__ emb,
                              float* __restrict__ out) {
    int w    = blockIdx.x * (blockDim.x >> 5) + (threadIdx.x >> 5);
    int lane = threadIdx.x & 31;
    int b = w >> 1;
    int n = w & 1;

    int idx = (int)(g_packed[w] & 0xFFFFFFFFull);

    if (lane == 0) {
        out[(size_t)BATCH * DLAT + w] = (float)idx;
        atomicAdd(&g_counts[n * KCODES + idx], 1);
    }

    const float* e  = emb + ((size_t)n * KCODES + idx) * DSUB;
    const float* zp = z   + (size_t)b * DLAT + n * DSUB;
    float*       op = out + (size_t)b * DLAT + n * DSUB;

    float s = 0.f;
#pragma unroll
    for (int t = 0; t < DSUB / 32; t++) {
        float ev = e[lane + 32 * t];
        float zv = zp[lane + 32 * t];
        float r  = __fsub_rn(ev, zv);
        op[lane + 32 * t] = __fadd_rn(zv, r);
        float d = __fsub_rn(zv, ev);
        s = __fmaf_rn(d, d, s);
    }
#pragma unroll
    for (int o = 16; o; o >>= 1) s += __shfl_down_sync(0xffffffffu, s, o);
    if (lane == 0) atomicAdd(&g_sse, (double)s);
}

// ---------------------------------------------------------------------------
__global__ void final_kernel(float* __restrict__ out) {
    __shared__ float red[256];
    int tid = threadIdx.x;
    float s = 0.f;
    for (int k = tid; k < KCODES; k += 256) {
        float p = (float)(g_counts[k] + g_counts[KCODES + k]) /
                  (float)(NCB * BATCH);
        s += p * logf(p + 1e-10f);
    }
    red[tid] = s;
    __syncthreads();
    for (int o = 128; o; o >>= 1) {
        if (tid < o) red[tid] += red[tid + o];
        __syncthreads();
    }
    if (tid == 0) {
        size_t off = (size_t)BATCH * DLAT + (size_t)NROWS;
        out[off + 0] = (float)(0.25 * (g_sse / (double)((size_t)BATCH * DLAT)));
        out[off + 1] = 0.0f;
        out[off + 2] = expf(-red[0]);
    }
}

// ---------------------------------------------------------------------------
extern "C" void kernel_launch(void* const* d_in, const int* in_sizes, int n_in,
                              void* d_out, int out_size) {
    const float* z   = (const float*)d_in[0];   // [8192, 512]
    const float* emb = (const float*)d_in[1];   // [2, 8192, 256]
    float* out = (float*)d_out;

    init_kernel<<<(NROWS + 255) / 256, 256>>>();
    convert_kernel<<<(BATCH * DLAT + 255) / 256, 256>>>(z, emb);
    zsq_kernel<<<NROWS / 8, 256>>>(z);

    dim3 grid(KCODES / BN, BATCH / BM, NCB);
    screen_kernel<<<grid, 256>>>();

    rescore_kernel<<<NROWS / 8, 256>>>(z, emb);
    gather_kernel<<<NROWS / 8, 256>>>(z, emb, out);
    final_kernel<<<1, 256>>>(out);
}